// round 1
// baseline (speedup 1.0000x reference)
#include <cuda_runtime.h>
#include <cstdint>

// ---------------------------------------------------------------------------
// GRUSeq2Seq on GB300 (sm_103a)
// Strategy: batch-partitioned persistent CTAs. 128 blocks x 16 batch rows.
// Each block runs the full 336-step encoder + 168-step autoregressive decoder
// for its 16 rows. All recurrent state in shared memory; fp32 throughout via
// packed fma.rn.f32x2 (2 MACs/instr). Weights pre-transposed to [k][j]-pair
// layout (one transform kernel pass) and streamed from L2 with coalesced
// LDG.64.
// ---------------------------------------------------------------------------

#define HID   128
#define NFEAT 16
#define TIN   336
#define TOUT  168
#define BATCH 2048
#define NP    8          // row pairs per block (16 rows, f32x2-packed)
#define NT    384        // threads per block (= 3*HID gate columns)
#define NBLK  (BATCH/16) // 128

typedef unsigned long long ull;

// ------------------------- transposed weight scratch -----------------------
__device__ float g_We0i[NFEAT * 384];  // enc layer0 Wih^T  [16][384] pair-interleaved
__device__ float g_We0h[HID * 384];    // enc layer0 Whh^T
__device__ float g_We1i[HID * 384];    // enc layer1 Wih^T
__device__ float g_We1h[HID * 384];    // enc layer1 Whh^T
__device__ float g_Wd0h[HID * 384];    // dec cell0 Whh^T
__device__ float g_Wd1i[HID * 384];    // dec cell1 Wih^T
__device__ float g_Wd1h[HID * 384];    // dec cell1 Whh^T
__device__ float g_Wfc1[HID * 64];     // fc1 W^T           [128][64]

// ------------------------- packed f32x2 helpers ----------------------------
__device__ __forceinline__ ull pk2(float lo, float hi) {
    ull r;
    asm("mov.b64 %0, {%1, %2};" : "=l"(r) : "f"(lo), "f"(hi));
    return r;
}
__device__ __forceinline__ float2 upk(ull v) {
    float a, b;
    asm("mov.b64 {%0, %1}, %2;" : "=f"(a), "=f"(b) : "l"(v));
    return make_float2(a, b);
}
__device__ __forceinline__ ull ffma2(ull a, ull b, ull c) {
    ull d;
    asm("fma.rn.f32x2 %0, %1, %2, %3;" : "=l"(d) : "l"(a), "l"(b), "l"(c));
    return d;
}

__device__ __forceinline__ float sigmf(float v) {
    return 1.0f / (1.0f + __expf(-v));
}
__device__ __forceinline__ float tanh_f(float v) {
    float e = __expf(-2.0f * fabsf(v));
    float t = (1.0f - e) / (1.0f + e);
    return copysignf(t, v);
}

// ------------------------- per-column GEMM core ----------------------------
// acc[p] += sum_k h2[p][k] * W[k][j]  over all K, W in pair-interleaved layout:
// float2 element [k/2][j] holds (W[k][j], W[k+1][j]).
template <int K, int N>
__device__ __forceinline__ void gemmf(const float2* __restrict__ W,
                                      const ull* __restrict__ hs,  // [NP][K]
                                      ull acc[NP], int j) {
#pragma unroll 4
    for (int k2 = 0; k2 < K / 2; k2++) {
        float2 w = __ldg(&W[k2 * N + j]);
        ull W0 = pk2(w.x, w.x);
        ull W1 = pk2(w.y, w.y);
#pragma unroll
        for (int p = 0; p < NP; p++) {
            ulonglong2 hv = *reinterpret_cast<const ulonglong2*>(&hs[p * K + 2 * k2]);
            acc[p] = ffma2(hv.x, W0, acc[p]);
            acc[p] = ffma2(hv.y, W1, acc[p]);
        }
    }
}

// ------------------------- GRU gate phase ----------------------------------
// gi/gh: [NP][384] packed pairs. hs: [NP][128]. Updates hs in place.
__device__ __forceinline__ void gates_phase(ull* hs, const ull* gi, const ull* gh,
                                            const float* bih, const float* bhh,
                                            int tid) {
    for (int i = tid; i < HID * NP; i += NT) {
        int u = i & (HID - 1);
        int p = i >> 7;
        float2 ir  = upk(gi[p * 384 + u]);
        float2 iz  = upk(gi[p * 384 + HID + u]);
        float2 inn = upk(gi[p * 384 + 2 * HID + u]);
        float2 hr  = upk(gh[p * 384 + u]);
        float2 hz  = upk(gh[p * 384 + HID + u]);
        float2 hn  = upk(gh[p * 384 + 2 * HID + u]);
        float br  = bih[u] + bhh[u];
        float bz  = bih[HID + u] + bhh[HID + u];
        float bin = bih[2 * HID + u];
        float bhn = bhh[2 * HID + u];
        float2 h = upk(hs[p * HID + u]);
        float rx = sigmf(ir.x + hr.x + br);
        float ry = sigmf(ir.y + hr.y + br);
        float zx = sigmf(iz.x + hz.x + bz);
        float zy = sigmf(iz.y + hz.y + bz);
        float nx = tanh_f(inn.x + bin + rx * (hn.x + bhn));
        float ny = tanh_f(inn.y + bin + ry * (hn.y + bhn));
        float ox = (1.0f - zx) * nx + zx * h.x;
        float oy = (1.0f - zy) * ny + zy * h.y;
        hs[p * HID + u] = pk2(ox, oy);
    }
}

// ------------------------- weight transform --------------------------------
// dst (pair-interleaved transposed): float index (k>>1)*(2J) + 2j + (k&1)
__global__ void tr_kernel(const float* __restrict__ src, int J, int K, int which) {
    float* dst = which == 0 ? g_We0i
               : which == 1 ? g_We0h
               : which == 2 ? g_We1i
               : which == 3 ? g_We1h
               : which == 4 ? g_Wd0h
               : which == 5 ? g_Wd1i
               : which == 6 ? g_Wd1h
                            : g_Wfc1;
    int i = blockIdx.x * blockDim.x + threadIdx.x;
    int n = J * K;
    if (i < n) {
        int j = i / K;
        int k = i % K;
        dst[(k >> 1) * (2 * J) + 2 * j + (k & 1)] = src[i];
    }
}

// ------------------------- shared memory layout -----------------------------
// (in ull units unless noted)
//   h0s   [NP*128]   = 1024
//   h1s   [NP*128]   = 1024
//   xs    [NP*16]    = 128
//   gi    [NP*384]   = 3072
//   gh    [NP*384]   = 3072
//   sb    8*384 f32  = 12288 B
//   sfcb1 64 f32, sw2 64 f32 = 512 B
//   fch   [NP*64]    = 512 ull
//   pred2 [NP]       = 8 ull
#define SMEM_BYTES (8320ull * 8 + 12800 + 512 * 8 + 64)

__global__ void __launch_bounds__(NT) gru_main(
    const float* __restrict__ x,
    const float* __restrict__ be_ih0, const float* __restrict__ be_hh0,
    const float* __restrict__ be_ih1, const float* __restrict__ be_hh1,
    const float* __restrict__ dwih0,
    const float* __restrict__ bd_ih0, const float* __restrict__ bd_hh0,
    const float* __restrict__ bd_ih1, const float* __restrict__ bd_hh1,
    const float* __restrict__ fcb1, const float* __restrict__ fcw2,
    const float* __restrict__ fcb2,
    float* __restrict__ out) {
    extern __shared__ ull sm[];
    ull* h0s = sm;
    ull* h1s = h0s + 1024;
    ull* xs  = h1s + 1024;
    ull* gi  = xs + 128;
    ull* gh  = gi + 3072;
    float* sb    = reinterpret_cast<float*>(gh + 3072);  // 8*384 floats
    float* sfcb1 = sb + 8 * 384;
    float* sw2   = sfcb1 + 64;
    ull* fch   = reinterpret_cast<ull*>(sw2 + 64);  // byte offset divisible by 16
    ull* pred2 = fch + NP * 64;

    const int tid = threadIdx.x;
    const int rowbase = blockIdx.x * 16;

    // init hidden state + biases
    for (int i = tid; i < 1024; i += NT) { h0s[i] = 0ull; h1s[i] = 0ull; }
    {
        const float* bsrc[8] = {be_ih0, be_hh0, be_ih1, be_hh1,
                                bd_ih0, bd_hh0, bd_ih1, bd_hh1};
#pragma unroll
        for (int a = 0; a < 8; a++) sb[a * 384 + tid] = bsrc[a][tid];
        if (tid < 64) { sfcb1[tid] = fcb1[tid]; sw2[tid] = fcw2[tid]; }
    }
    __syncthreads();

    ull acc[NP];
    const int j = tid;

    // =============================== encoder ===============================
    for (int t = 0; t < TIN; t++) {
        // stage x_t (pair-packed)
        for (int i = tid; i < NP * NFEAT; i += NT) {
            int p = i >> 4, c = i & 15;
            size_t r0 = (size_t)(rowbase + 2 * p) * TIN * NFEAT + (size_t)t * NFEAT + c;
            float a = x[r0];
            float b = x[r0 + (size_t)TIN * NFEAT];
            xs[p * NFEAT + c] = pk2(a, b);
        }
        __syncthreads();

        // ---- layer 0 ----
#pragma unroll
        for (int p = 0; p < NP; p++) acc[p] = 0ull;
        gemmf<NFEAT, 384>(reinterpret_cast<const float2*>(g_We0i), xs, acc, j);
#pragma unroll
        for (int p = 0; p < NP; p++) gi[p * 384 + j] = acc[p];

#pragma unroll
        for (int p = 0; p < NP; p++) acc[p] = 0ull;
        gemmf<HID, 384>(reinterpret_cast<const float2*>(g_We0h), h0s, acc, j);
#pragma unroll
        for (int p = 0; p < NP; p++) gh[p * 384 + j] = acc[p];
        __syncthreads();
        gates_phase(h0s, gi, gh, sb + 0 * 384, sb + 1 * 384, tid);
        __syncthreads();

        // ---- layer 1 (input = new h0) ----
#pragma unroll
        for (int p = 0; p < NP; p++) acc[p] = 0ull;
        gemmf<HID, 384>(reinterpret_cast<const float2*>(g_We1i), h0s, acc, j);
#pragma unroll
        for (int p = 0; p < NP; p++) gi[p * 384 + j] = acc[p];

#pragma unroll
        for (int p = 0; p < NP; p++) acc[p] = 0ull;
        gemmf<HID, 384>(reinterpret_cast<const float2*>(g_We1h), h1s, acc, j);
#pragma unroll
        for (int p = 0; p < NP; p++) gh[p * 384 + j] = acc[p];
        __syncthreads();
        gates_phase(h1s, gi, gh, sb + 2 * 384, sb + 3 * 384, tid);
        __syncthreads();
    }

    // =============================== decoder ===============================
    if (tid < NP) pred2[tid] = 0ull;
    __syncthreads();

    const float b2 = __ldg(fcb2);

    for (int t = 0; t < TOUT; t++) {
        // ---- cell 0: gi = pred * Wih0 (K=1), gh = h0 @ Whh0^T ----
        {
            float wj = __ldg(&dwih0[j]);
            ull Wj = pk2(wj, wj);
#pragma unroll
            for (int p = 0; p < NP; p++) gi[p * 384 + j] = ffma2(pred2[p], Wj, 0ull);
        }
#pragma unroll
        for (int p = 0; p < NP; p++) acc[p] = 0ull;
        gemmf<HID, 384>(reinterpret_cast<const float2*>(g_Wd0h), h0s, acc, j);
#pragma unroll
        for (int p = 0; p < NP; p++) gh[p * 384 + j] = acc[p];
        __syncthreads();
        gates_phase(h0s, gi, gh, sb + 4 * 384, sb + 5 * 384, tid);
        __syncthreads();

        // ---- cell 1: input = new h0 ----
#pragma unroll
        for (int p = 0; p < NP; p++) acc[p] = 0ull;
        gemmf<HID, 384>(reinterpret_cast<const float2*>(g_Wd1i), h0s, acc, j);
#pragma unroll
        for (int p = 0; p < NP; p++) gi[p * 384 + j] = acc[p];

#pragma unroll
        for (int p = 0; p < NP; p++) acc[p] = 0ull;
        gemmf<HID, 384>(reinterpret_cast<const float2*>(g_Wd1h), h1s, acc, j);
#pragma unroll
        for (int p = 0; p < NP; p++) gh[p * 384 + j] = acc[p];
        __syncthreads();
        gates_phase(h1s, gi, gh, sb + 6 * 384, sb + 7 * 384, tid);
        __syncthreads();

        // ---- fc1: 64 cols x 8 pairs, K=128, relu ----
        for (int i = tid; i < 64 * NP; i += NT) {
            int c = i & 63, p = i >> 6;
            ull a0 = 0ull, a1 = 0ull;
            const float2* W = reinterpret_cast<const float2*>(g_Wfc1);
#pragma unroll 8
            for (int k2 = 0; k2 < HID / 2; k2++) {
                float2 w = __ldg(&W[k2 * 64 + c]);
                ulonglong2 hv =
                    *reinterpret_cast<const ulonglong2*>(&h1s[p * HID + 2 * k2]);
                a0 = ffma2(hv.x, pk2(w.x, w.x), a0);
                a1 = ffma2(hv.y, pk2(w.y, w.y), a1);
            }
            float2 s0 = upk(a0), s1 = upk(a1);
            float vx = fmaxf(s0.x + s1.x + sfcb1[c], 0.0f);
            float vy = fmaxf(s0.y + s1.y + sfcb1[c], 0.0f);
            fch[p * 64 + c] = pk2(vx, vy);
        }
        __syncthreads();

        // ---- fc2 + writeback + feedback ----
        if (tid < NP) {
            int p = tid;
            ull a0 = 0ull, a1 = 0ull;
#pragma unroll
            for (int k = 0; k < 64; k += 2) {
                a0 = ffma2(fch[p * 64 + k], pk2(sw2[k], sw2[k]), a0);
                a1 = ffma2(fch[p * 64 + k + 1], pk2(sw2[k + 1], sw2[k + 1]), a1);
            }
            float2 s0 = upk(a0), s1 = upk(a1);
            float px = fmaxf(s0.x + s1.x + b2, 0.0f);
            float py = fmaxf(s0.y + s1.y + b2, 0.0f);
            pred2[p] = pk2(px, py);
            out[(size_t)(rowbase + 2 * p) * TOUT + t] = px;
            out[(size_t)(rowbase + 2 * p + 1) * TOUT + t] = py;
        }
        __syncthreads();
    }
}

// ---------------------------------------------------------------------------
extern "C" void kernel_launch(void* const* d_in, const int* in_sizes, int n_in,
                              void* d_out, int out_size) {
    (void)in_sizes; (void)n_in; (void)out_size;
    const float* x        = (const float*)d_in[0];
    const float* eWih0    = (const float*)d_in[1];
    const float* eWhh0    = (const float*)d_in[2];
    const float* ebih0    = (const float*)d_in[3];
    const float* ebhh0    = (const float*)d_in[4];
    const float* eWih1    = (const float*)d_in[5];
    const float* eWhh1    = (const float*)d_in[6];
    const float* ebih1    = (const float*)d_in[7];
    const float* ebhh1    = (const float*)d_in[8];
    const float* dWih0    = (const float*)d_in[9];
    const float* dWhh0    = (const float*)d_in[10];
    const float* dbih0    = (const float*)d_in[11];
    const float* dbhh0    = (const float*)d_in[12];
    const float* dWih1    = (const float*)d_in[13];
    const float* dWhh1    = (const float*)d_in[14];
    const float* dbih1    = (const float*)d_in[15];
    const float* dbhh1    = (const float*)d_in[16];
    const float* fcW1     = (const float*)d_in[17];
    const float* fcb1     = (const float*)d_in[18];
    const float* fcW2     = (const float*)d_in[19];
    const float* fcb2     = (const float*)d_in[20];
    float* out = (float*)d_out;

    cudaFuncSetAttribute(gru_main, cudaFuncAttributeMaxDynamicSharedMemorySize,
                         (int)SMEM_BYTES);

    // weight transforms (deterministic, re-run each call)
    {
        int thr = 256;
        tr_kernel<<<(384 * NFEAT + thr - 1) / thr, thr>>>(eWih0, 384, NFEAT, 0);
        tr_kernel<<<(384 * HID + thr - 1) / thr, thr>>>(eWhh0, 384, HID, 1);
        tr_kernel<<<(384 * HID + thr - 1) / thr, thr>>>(eWih1, 384, HID, 2);
        tr_kernel<<<(384 * HID + thr - 1) / thr, thr>>>(eWhh1, 384, HID, 3);
        tr_kernel<<<(384 * HID + thr - 1) / thr, thr>>>(dWhh0, 384, HID, 4);
        tr_kernel<<<(384 * HID + thr - 1) / thr, thr>>>(dWih1, 384, HID, 5);
        tr_kernel<<<(384 * HID + thr - 1) / thr, thr>>>(dWhh1, 384, HID, 6);
        tr_kernel<<<(64 * HID + thr - 1) / thr, thr>>>(fcW1, 64, HID, 7);
    }

    gru_main<<<NBLK, NT, SMEM_BYTES>>>(x,
                                       ebih0, ebhh0, ebih1, ebhh1,
                                       dWih0,
                                       dbih0, dbhh0, dbih1, dbhh1,
                                       fcb1, fcW2, fcb2,
                                       out);
}

// round 2
// speedup vs baseline: 1.0869x; 1.0869x over previous
#include <cuda_runtime.h>
#include <cstdint>

// ---------------------------------------------------------------------------
// GRUSeq2Seq on GB300 (sm_103a) — round 2
// 147 persistent CTAs x 14 batch rows (7 f32x2 pairs). 768 threads/CTA:
// thread-halves split the K dimension of every hidden GEMM (K-split), gates
// phase sums the two partial buffers. Weights pre-transposed to float4
// [k/4][j][4] layout for LDG.128. fp32 throughout via fma.rn.f32x2.
// ---------------------------------------------------------------------------

#define HID   128
#define NFEAT 16
#define TIN   336
#define TOUT  168
#define BATCH 2048
#define NP    7           // row pairs per block (14 rows)
#define NROW  (2*NP)      // 14
#define NT    768
#define NBLK  147         // 147*14 = 2058 >= 2048

typedef unsigned long long ull;

// ------------------------- transposed weight scratch -----------------------
__device__ float g_We0i[NFEAT * 384];  // float4 layout [k/4][384][4]
__device__ float g_We0h[HID * 384];
__device__ float g_We1i[HID * 384];
__device__ float g_We1h[HID * 384];
__device__ float g_Wd0h[HID * 384];
__device__ float g_Wd1i[HID * 384];
__device__ float g_Wd1h[HID * 384];
__device__ float g_Wfc1[HID * 64];     // pair layout [k/2][64][2]

// ------------------------- packed f32x2 helpers ----------------------------
__device__ __forceinline__ ull pk2(float lo, float hi) {
    ull r;
    asm("mov.b64 %0, {%1, %2};" : "=l"(r) : "f"(lo), "f"(hi));
    return r;
}
__device__ __forceinline__ float2 upk(ull v) {
    float a, b;
    asm("mov.b64 {%0, %1}, %2;" : "=f"(a), "=f"(b) : "l"(v));
    return make_float2(a, b);
}
__device__ __forceinline__ ull ffma2(ull a, ull b, ull c) {
    ull d;
    asm("fma.rn.f32x2 %0, %1, %2, %3;" : "=l"(d) : "l"(a), "l"(b), "l"(c));
    return d;
}
__device__ __forceinline__ ull add2(ull a, ull b) {
    ull d;
    asm("add.rn.f32x2 %0, %1, %2;" : "=l"(d) : "l"(a), "l"(b));
    return d;
}

__device__ __forceinline__ float sigmf(float v) {
    return 1.0f / (1.0f + __expf(-v));
}
__device__ __forceinline__ float tanh_f(float v) {
    float e = __expf(-2.0f * fabsf(v));
    float t = (1.0f - e) / (1.0f + e);
    return copysignf(t, v);
}

// ------------------------- half-K GEMM core ---------------------------------
// Computes dst[p][j] = sum over this thread-half's K range of
//   hs[p][k] (f32x2 pair of 2 batch rows) * W[k][j].
// W float4 layout: W4[k4*384 + j] = (W[4k4][j], W[4k4+1][j], W[4k4+2][j], W[4k4+3][j])
template <int K>
__device__ __forceinline__ void gemm_half(const float4* __restrict__ W4,
                                          const ull* __restrict__ hs,
                                          ull* __restrict__ dst,
                                          int j, int half) {
    constexpr int K4  = K / 4;
    constexpr int HK4 = K4 / 2;
    const int k4b = half * HK4;
    ull acc[NP];
#pragma unroll
    for (int p = 0; p < NP; p++) acc[p] = 0ull;
#pragma unroll 2
    for (int i = 0; i < HK4; i++) {
        int k4 = k4b + i;
        float4 w = __ldg(&W4[k4 * 384 + j]);
        ull w0 = pk2(w.x, w.x);
        ull w1 = pk2(w.y, w.y);
        ull w2 = pk2(w.z, w.z);
        ull w3 = pk2(w.w, w.w);
#pragma unroll
        for (int p = 0; p < NP; p++) {
            const ull* hp = &hs[p * K + 4 * k4];
            ulonglong2 h01 = *reinterpret_cast<const ulonglong2*>(hp);
            ulonglong2 h23 = *reinterpret_cast<const ulonglong2*>(hp + 2);
            acc[p] = ffma2(h01.x, w0, acc[p]);
            acc[p] = ffma2(h01.y, w1, acc[p]);
            acc[p] = ffma2(h23.x, w2, acc[p]);
            acc[p] = ffma2(h23.y, w3, acc[p]);
        }
    }
#pragma unroll
    for (int p = 0; p < NP; p++) dst[p * 384 + j] = acc[p];
}

// ------------------------- GRU gate phase ----------------------------------
__device__ __forceinline__ void gates_phase(ull* hs,
                                            const ull* gil, const ull* gih,
                                            const ull* ghl, const ull* ghh,
                                            const float* bih, const float* bhh,
                                            int tid) {
    for (int i = tid; i < HID * NP; i += NT) {
        int u = i & (HID - 1);
        int p = i >> 7;
        int b0 = p * 384 + u;
        float2 ir  = upk(add2(gil[b0], gih[b0]));
        float2 iz  = upk(add2(gil[b0 + HID], gih[b0 + HID]));
        float2 inn = upk(add2(gil[b0 + 2 * HID], gih[b0 + 2 * HID]));
        float2 hr  = upk(add2(ghl[b0], ghh[b0]));
        float2 hz  = upk(add2(ghl[b0 + HID], ghh[b0 + HID]));
        float2 hn  = upk(add2(ghl[b0 + 2 * HID], ghh[b0 + 2 * HID]));
        float br  = bih[u] + bhh[u];
        float bz  = bih[HID + u] + bhh[HID + u];
        float bin = bih[2 * HID + u];
        float bhn = bhh[2 * HID + u];
        float2 h = upk(hs[p * HID + u]);
        float rx = sigmf(ir.x + hr.x + br);
        float ry = sigmf(ir.y + hr.y + br);
        float zx = sigmf(iz.x + hz.x + bz);
        float zy = sigmf(iz.y + hz.y + bz);
        float nx = tanh_f(inn.x + bin + rx * (hn.x + bhn));
        float ny = tanh_f(inn.y + bin + ry * (hn.y + bhn));
        float ox = (1.0f - zx) * nx + zx * h.x;
        float oy = (1.0f - zy) * ny + zy * h.y;
        hs[p * HID + u] = pk2(ox, oy);
    }
}

// ------------------------- weight transform --------------------------------
// which 0..6: float4 layout dst[(k>>2)*(4*J) + 4*j + (k&3)]
// which 7   : pair   layout dst[(k>>1)*(2*J) + 2*j + (k&1)]
__global__ void tr_kernel(const float* __restrict__ src, int J, int K, int which) {
    float* dst = which == 0 ? g_We0i
               : which == 1 ? g_We0h
               : which == 2 ? g_We1i
               : which == 3 ? g_We1h
               : which == 4 ? g_Wd0h
               : which == 5 ? g_Wd1i
               : which == 6 ? g_Wd1h
                            : g_Wfc1;
    int i = blockIdx.x * blockDim.x + threadIdx.x;
    int n = J * K;
    if (i < n) {
        int j = i / K;
        int k = i % K;
        if (which == 7)
            dst[(k >> 1) * (2 * J) + 2 * j + (k & 1)] = src[i];
        else
            dst[(k >> 2) * (4 * J) + 4 * j + (k & 3)] = src[i];
    }
}

// ------------------------- shared memory layout (ull units) -----------------
//   h0s   NP*128 = 896
//   h1s   896
//   xs    NP*16  = 112
//   gil/gih/ghl/ghh  4 * NP*384 = 10752
//   fch   NP*64 = 448
//   pred2 8
//   sb    8*384 f32 = 1536 ull
//   sfcb1+sw2 128 f32 = 64 ull
#define SM_ULL (896 + 896 + 112 + 10752 + 448 + 8 + 1536 + 64)
#define SMEM_BYTES (SM_ULL * 8)

__global__ void __launch_bounds__(NT) gru_main(
    const float* __restrict__ x,
    const float* __restrict__ be_ih0, const float* __restrict__ be_hh0,
    const float* __restrict__ be_ih1, const float* __restrict__ be_hh1,
    const float* __restrict__ dwih0,
    const float* __restrict__ bd_ih0, const float* __restrict__ bd_hh0,
    const float* __restrict__ bd_ih1, const float* __restrict__ bd_hh1,
    const float* __restrict__ fcb1, const float* __restrict__ fcw2,
    const float* __restrict__ fcb2,
    float* __restrict__ out) {
    extern __shared__ ull sm[];
    ull* h0s = sm;                 // 896
    ull* h1s = h0s + 896;          // 896
    ull* xs  = h1s + 896;          // 112
    ull* gil = xs + 112;           // 2688
    ull* gih = gil + NP * 384;     // 2688
    ull* ghl = gih + NP * 384;     // 2688
    ull* ghh = ghl + NP * 384;     // 2688
    ull* fch   = ghh + NP * 384;   // 448
    ull* pred2 = fch + NP * 64;    // 8
    float* sb    = reinterpret_cast<float*>(pred2 + 8);   // 8*384
    float* sfcb1 = sb + 8 * 384;
    float* sw2   = sfcb1 + 64;

    const int tid  = threadIdx.x;
    const int half = (tid >= 384) ? 1 : 0;
    const int j    = half ? tid - 384 : tid;
    const int rowbase = blockIdx.x * NROW;

    // init
    for (int i = tid; i < 2 * 896; i += NT) h0s[i] = 0ull;   // h0s+h1s contiguous
    if (tid < 384) {
        const float* bsrc[8] = {be_ih0, be_hh0, be_ih1, be_hh1,
                                bd_ih0, bd_hh0, bd_ih1, bd_hh1};
#pragma unroll
        for (int a = 0; a < 8; a++) sb[a * 384 + tid] = bsrc[a][tid];
    }
    if (tid < 64) { sfcb1[tid] = fcb1[tid]; sw2[tid] = fcw2[tid]; }
    if (tid < 8) pred2[tid] = 0ull;
    __syncthreads();

    // =============================== encoder ===============================
    for (int t = 0; t < TIN; t++) {
        // stage x_t (pair-packed, clamp OOB rows)
        for (int i = tid; i < NP * NFEAT; i += NT) {
            int p = i >> 4, c = i & 15;
            int ra = rowbase + 2 * p;
            int rb = ra + 1;
            if (ra > BATCH - 1) ra = BATCH - 1;
            if (rb > BATCH - 1) rb = BATCH - 1;
            float a = x[(size_t)ra * TIN * NFEAT + (size_t)t * NFEAT + c];
            float b = x[(size_t)rb * TIN * NFEAT + (size_t)t * NFEAT + c];
            xs[p * NFEAT + c] = pk2(a, b);
        }
        __syncthreads();

        // layer 0
        gemm_half<NFEAT>(reinterpret_cast<const float4*>(g_We0i), xs,
                         half ? gih : gil, j, half);
        gemm_half<HID>(reinterpret_cast<const float4*>(g_We0h), h0s,
                       half ? ghh : ghl, j, half);
        __syncthreads();
        gates_phase(h0s, gil, gih, ghl, ghh, sb + 0 * 384, sb + 1 * 384, tid);
        __syncthreads();

        // layer 1 (input = new h0)
        gemm_half<HID>(reinterpret_cast<const float4*>(g_We1i), h0s,
                       half ? gih : gil, j, half);
        gemm_half<HID>(reinterpret_cast<const float4*>(g_We1h), h1s,
                       half ? ghh : ghl, j, half);
        __syncthreads();
        gates_phase(h1s, gil, gih, ghl, ghh, sb + 2 * 384, sb + 3 * 384, tid);
        __syncthreads();
    }

    // =============================== decoder ===============================
    const float b2 = __ldg(fcb2);

    for (int t = 0; t < TOUT; t++) {
        // cell 0: gi = pred * Wih0 (K=1) done by lo half; hi half zeros
        {
            if (!half) {
                float wj = __ldg(&dwih0[j]);
                ull Wj = pk2(wj, wj);
#pragma unroll
                for (int p = 0; p < NP; p++)
                    gil[p * 384 + j] = ffma2(pred2[p], Wj, 0ull);
            } else {
#pragma unroll
                for (int p = 0; p < NP; p++) gih[p * 384 + j] = 0ull;
            }
        }
        gemm_half<HID>(reinterpret_cast<const float4*>(g_Wd0h), h0s,
                       half ? ghh : ghl, j, half);
        __syncthreads();
        gates_phase(h0s, gil, gih, ghl, ghh, sb + 4 * 384, sb + 5 * 384, tid);
        __syncthreads();

        // cell 1 (input = new h0)
        gemm_half<HID>(reinterpret_cast<const float4*>(g_Wd1i), h0s,
                       half ? gih : gil, j, half);
        gemm_half<HID>(reinterpret_cast<const float4*>(g_Wd1h), h1s,
                       half ? ghh : ghl, j, half);
        __syncthreads();
        gates_phase(h1s, gil, gih, ghl, ghh, sb + 6 * 384, sb + 7 * 384, tid);
        __syncthreads();

        // fc1: 64 cols x NP pairs, K=128, relu
        if (tid < 64 * NP) {
            int c = tid & 63, p = tid >> 6;
            ull a0 = 0ull, a1 = 0ull;
            const float2* W = reinterpret_cast<const float2*>(g_Wfc1);
#pragma unroll 8
            for (int k2 = 0; k2 < HID / 2; k2++) {
                float2 w = __ldg(&W[k2 * 64 + c]);
                ulonglong2 hv =
                    *reinterpret_cast<const ulonglong2*>(&h1s[p * HID + 2 * k2]);
                a0 = ffma2(hv.x, pk2(w.x, w.x), a0);
                a1 = ffma2(hv.y, pk2(w.y, w.y), a1);
            }
            float2 s0 = upk(a0), s1 = upk(a1);
            float vx = fmaxf(s0.x + s1.x + sfcb1[c], 0.0f);
            float vy = fmaxf(s0.y + s1.y + sfcb1[c], 0.0f);
            fch[p * 64 + c] = pk2(vx, vy);
        }
        __syncthreads();

        // fc2 + writeback + feedback: warp p handles pair p
        if (tid < 32 * NP) {
            int p = tid >> 5, l = tid & 31;
            ull a = ffma2(fch[p * 64 + 2 * l], pk2(sw2[2 * l], sw2[2 * l]), 0ull);
            a = ffma2(fch[p * 64 + 2 * l + 1],
                      pk2(sw2[2 * l + 1], sw2[2 * l + 1]), a);
            float2 s = upk(a);
#pragma unroll
            for (int o = 16; o > 0; o >>= 1) {
                s.x += __shfl_down_sync(0xffffffffu, s.x, o);
                s.y += __shfl_down_sync(0xffffffffu, s.y, o);
            }
            if (l == 0) {
                float px = fmaxf(s.x + b2, 0.0f);
                float py = fmaxf(s.y + b2, 0.0f);
                pred2[p] = pk2(px, py);
                int ra = rowbase + 2 * p;
                if (ra < BATCH) out[(size_t)ra * TOUT + t] = px;
                if (ra + 1 < BATCH) out[(size_t)(ra + 1) * TOUT + t] = py;
            }
        }
        __syncthreads();
    }
}

// ---------------------------------------------------------------------------
extern "C" void kernel_launch(void* const* d_in, const int* in_sizes, int n_in,
                              void* d_out, int out_size) {
    (void)in_sizes; (void)n_in; (void)out_size;
    const float* x     = (const float*)d_in[0];
    const float* eWih0 = (const float*)d_in[1];
    const float* eWhh0 = (const float*)d_in[2];
    const float* ebih0 = (const float*)d_in[3];
    const float* ebhh0 = (const float*)d_in[4];
    const float* eWih1 = (const float*)d_in[5];
    const float* eWhh1 = (const float*)d_in[6];
    const float* ebih1 = (const float*)d_in[7];
    const float* ebhh1 = (const float*)d_in[8];
    const float* dWih0 = (const float*)d_in[9];
    const float* dWhh0 = (const float*)d_in[10];
    const float* dbih0 = (const float*)d_in[11];
    const float* dbhh0 = (const float*)d_in[12];
    const float* dWih1 = (const float*)d_in[13];
    const float* dWhh1 = (const float*)d_in[14];
    const float* dbih1 = (const float*)d_in[15];
    const float* dbhh1 = (const float*)d_in[16];
    const float* fcW1  = (const float*)d_in[17];
    const float* fcb1  = (const float*)d_in[18];
    const float* fcW2  = (const float*)d_in[19];
    const float* fcb2  = (const float*)d_in[20];
    float* out = (float*)d_out;

    cudaFuncSetAttribute(gru_main, cudaFuncAttributeMaxDynamicSharedMemorySize,
                         (int)SMEM_BYTES);

    {
        int thr = 256;
        tr_kernel<<<(384 * NFEAT + thr - 1) / thr, thr>>>(eWih0, 384, NFEAT, 0);
        tr_kernel<<<(384 * HID + thr - 1) / thr, thr>>>(eWhh0, 384, HID, 1);
        tr_kernel<<<(384 * HID + thr - 1) / thr, thr>>>(eWih1, 384, HID, 2);
        tr_kernel<<<(384 * HID + thr - 1) / thr, thr>>>(eWhh1, 384, HID, 3);
        tr_kernel<<<(384 * HID + thr - 1) / thr, thr>>>(dWhh0, 384, HID, 4);
        tr_kernel<<<(384 * HID + thr - 1) / thr, thr>>>(dWih1, 384, HID, 5);
        tr_kernel<<<(384 * HID + thr - 1) / thr, thr>>>(dWhh1, 384, HID, 6);
        tr_kernel<<<(64 * HID + thr - 1) / thr, thr>>>(fcW1, 64, HID, 7);
    }

    gru_main<<<NBLK, NT, SMEM_BYTES>>>(x,
                                       ebih0, ebhh0, ebih1, ebhh1,
                                       dWih0,
                                       dbih0, dbhh0, dbih1, dbhh1,
                                       fcb1, fcW2, fcb2,
                                       out);
}

// round 3
// speedup vs baseline: 1.3413x; 1.2341x over previous
#include <cuda_runtime.h>
#include <cstdint>

// ---------------------------------------------------------------------------
// GRUSeq2Seq on GB300 (sm_103a) — round 3
// 147 persistent CTAs x 14 batch rows (7 f32x2 pairs). 768 threads/CTA:
//   tid -> (jt in [0,192)) x (rowgroup: pairs 0-3 / 4-6) x (K-half)
// Each thread computes TWO gate columns (jt, jt+192) so each h LDS.128 feeds
// 4 FFMA2 (halves LDS pressure). Weights float4 [k/4][384][4] via LDG.128.
// fp32 throughout via fma.rn.f32x2. Single fused transpose kernel.
// ---------------------------------------------------------------------------

#define HID   128
#define NFEAT 16
#define TIN   336
#define TOUT  168
#define BATCH 2048
#define NP    7           // row pairs per block (14 rows)
#define NROW  (2*NP)      // 14
#define NT    768
#define NBLK  147         // 147*14 = 2058 >= 2048

typedef unsigned long long ull;

// ------------------------- transposed weight scratch -----------------------
__device__ float g_We0i[NFEAT * 384];  // float4 layout [k/4][384][4]
__device__ float g_We0h[HID * 384];
__device__ float g_We1i[HID * 384];
__device__ float g_We1h[HID * 384];
__device__ float g_Wd0h[HID * 384];
__device__ float g_Wd1i[HID * 384];
__device__ float g_Wd1h[HID * 384];
__device__ float g_Wfc1[HID * 64];     // pair layout [k/2][64][2]

// ------------------------- packed f32x2 helpers ----------------------------
__device__ __forceinline__ ull pk2(float lo, float hi) {
    ull r;
    asm("mov.b64 %0, {%1, %2};" : "=l"(r) : "f"(lo), "f"(hi));
    return r;
}
__device__ __forceinline__ float2 upk(ull v) {
    float a, b;
    asm("mov.b64 {%0, %1}, %2;" : "=f"(a), "=f"(b) : "l"(v));
    return make_float2(a, b);
}
__device__ __forceinline__ ull ffma2(ull a, ull b, ull c) {
    ull d;
    asm("fma.rn.f32x2 %0, %1, %2, %3;" : "=l"(d) : "l"(a), "l"(b), "l"(c));
    return d;
}
__device__ __forceinline__ ull add2(ull a, ull b) {
    ull d;
    asm("add.rn.f32x2 %0, %1, %2;" : "=l"(d) : "l"(a), "l"(b));
    return d;
}

__device__ __forceinline__ float sigmf(float v) {
    return 1.0f / (1.0f + __expf(-v));
}
__device__ __forceinline__ float tanh_f(float v) {
    float e = __expf(-2.0f * fabsf(v));
    float t = (1.0f - e) / (1.0f + e);
    return copysignf(t, v);
}

// ------------------------- dual-column half-K GEMM core ---------------------
// Thread computes columns j0 and j0+192 for PC row-pairs starting at pbase,
// over its K-half. W float4 layout: W4[k4*384 + j] = W[4k4..4k4+3][j].
template <int K, int PC>
__device__ __forceinline__ void gemm2(const float4* __restrict__ W4,
                                      const ull* __restrict__ hs,
                                      ull* __restrict__ dst,
                                      int j0, int half, int pbase) {
    constexpr int HK4 = K / 8;  // float4 groups per K-half
    const int k4b = half * HK4;
    ull a0[PC], a1[PC];
#pragma unroll
    for (int p = 0; p < PC; p++) { a0[p] = 0ull; a1[p] = 0ull; }
#pragma unroll 2
    for (int i = 0; i < HK4; i++) {
        int k4 = k4b + i;
        float4 wa = __ldg(&W4[k4 * 384 + j0]);
        float4 wb = __ldg(&W4[k4 * 384 + j0 + 192]);
        ull wa0 = pk2(wa.x, wa.x), wa1 = pk2(wa.y, wa.y);
        ull wa2 = pk2(wa.z, wa.z), wa3 = pk2(wa.w, wa.w);
        ull wb0 = pk2(wb.x, wb.x), wb1 = pk2(wb.y, wb.y);
        ull wb2 = pk2(wb.z, wb.z), wb3 = pk2(wb.w, wb.w);
#pragma unroll
        for (int p = 0; p < PC; p++) {
            const ull* hp = &hs[(pbase + p) * K + 4 * k4];
            ulonglong2 h01 = *reinterpret_cast<const ulonglong2*>(hp);
            ulonglong2 h23 = *reinterpret_cast<const ulonglong2*>(hp + 2);
            a0[p] = ffma2(h01.x, wa0, a0[p]);
            a1[p] = ffma2(h01.x, wb0, a1[p]);
            a0[p] = ffma2(h01.y, wa1, a0[p]);
            a1[p] = ffma2(h01.y, wb1, a1[p]);
            a0[p] = ffma2(h23.x, wa2, a0[p]);
            a1[p] = ffma2(h23.x, wb2, a1[p]);
            a0[p] = ffma2(h23.y, wa3, a0[p]);
            a1[p] = ffma2(h23.y, wb3, a1[p]);
        }
    }
#pragma unroll
    for (int p = 0; p < PC; p++) {
        dst[(pbase + p) * 384 + j0]       = a0[p];
        dst[(pbase + p) * 384 + j0 + 192] = a1[p];
    }
}

// dispatch over rowgroup
template <int K>
__device__ __forceinline__ void gemm_d(const float* __restrict__ W,
                                       const ull* __restrict__ hs,
                                       ull* __restrict__ dst,
                                       int j0, int half, int rg) {
    const float4* W4 = reinterpret_cast<const float4*>(W);
    if (rg == 0) gemm2<K, 4>(W4, hs, dst, j0, half, 0);
    else         gemm2<K, 3>(W4, hs, dst, j0, half, 4);
}

// ------------------------- GRU gate phase ----------------------------------
__device__ __forceinline__ void gates_phase(ull* hs,
                                            const ull* gil, const ull* gih,
                                            const ull* ghl, const ull* ghh,
                                            const float* bih, const float* bhh,
                                            int tid) {
    for (int i = tid; i < HID * NP; i += NT) {
        int u = i & (HID - 1);
        int p = i >> 7;
        int b0 = p * 384 + u;
        float2 ir  = upk(add2(gil[b0], gih[b0]));
        float2 iz  = upk(add2(gil[b0 + HID], gih[b0 + HID]));
        float2 inn = upk(add2(gil[b0 + 2 * HID], gih[b0 + 2 * HID]));
        float2 hr  = upk(add2(ghl[b0], ghh[b0]));
        float2 hz  = upk(add2(ghl[b0 + HID], ghh[b0 + HID]));
        float2 hn  = upk(add2(ghl[b0 + 2 * HID], ghh[b0 + 2 * HID]));
        float br  = bih[u] + bhh[u];
        float bz  = bih[HID + u] + bhh[HID + u];
        float bin = bih[2 * HID + u];
        float bhn = bhh[2 * HID + u];
        float2 h = upk(hs[p * HID + u]);
        float rx = sigmf(ir.x + hr.x + br);
        float ry = sigmf(ir.y + hr.y + br);
        float zx = sigmf(iz.x + hz.x + bz);
        float zy = sigmf(iz.y + hz.y + bz);
        float nx = tanh_f(inn.x + bin + rx * (hn.x + bhn));
        float ny = tanh_f(inn.y + bin + ry * (hn.y + bhn));
        float ox = (1.0f - zx) * nx + zx * h.x;
        float oy = (1.0f - zy) * ny + zy * h.y;
        hs[p * HID + u] = pk2(ox, oy);
    }
}

// ------------------------- fused weight transform ---------------------------
// matrices 0..6: float4 layout dst[(k>>2)*(4*J) + 4*j + (k&3)], J=384
// matrix  7   : pair   layout dst[(k>>1)*(2*J) + 2*j + (k&1)], J=64
__global__ void tr_all(const float* __restrict__ w0, const float* __restrict__ w1,
                       const float* __restrict__ w2, const float* __restrict__ w3,
                       const float* __restrict__ w4, const float* __restrict__ w5,
                       const float* __restrict__ w6, const float* __restrict__ w7) {
    int i = blockIdx.x * blockDim.x + threadIdx.x;
    // segments
    const int n0 = NFEAT * 384;      // 6144
    const int nH = HID * 384;        // 49152
    const int n7 = HID * 64;         // 8192
    int seg, off;
    if (i < n0) { seg = 0; off = i; }
    else if (i < n0 + 6 * nH) { seg = 1 + (i - n0) / nH; off = (i - n0) % nH; }
    else if (i < n0 + 6 * nH + n7) { seg = 7; off = i - n0 - 6 * nH; }
    else return;

    const float* src = seg == 0 ? w0 : seg == 1 ? w1 : seg == 2 ? w2
                     : seg == 3 ? w3 : seg == 4 ? w4 : seg == 5 ? w5
                     : seg == 6 ? w6 : w7;
    float* dst = seg == 0 ? g_We0i : seg == 1 ? g_We0h : seg == 2 ? g_We1i
               : seg == 3 ? g_We1h : seg == 4 ? g_Wd0h : seg == 5 ? g_Wd1i
               : seg == 6 ? g_Wd1h : g_Wfc1;
    int K = seg == 0 ? NFEAT : HID;
    int J = seg == 7 ? 64 : 384;
    int j = off / K;
    int k = off % K;
    float v = src[off];
    if (seg == 7)
        dst[(k >> 1) * (2 * J) + 2 * j + (k & 1)] = v;
    else
        dst[(k >> 2) * (4 * J) + 4 * j + (k & 3)] = v;
}

// ------------------------- shared memory layout (ull units) -----------------
#define SM_ULL (896 + 896 + 112 + 10752 + 448 + 8 + 1536 + 64)
#define SMEM_BYTES (SM_ULL * 8)

__global__ void __launch_bounds__(NT) gru_main(
    const float* __restrict__ x,
    const float* __restrict__ be_ih0, const float* __restrict__ be_hh0,
    const float* __restrict__ be_ih1, const float* __restrict__ be_hh1,
    const float* __restrict__ dwih0,
    const float* __restrict__ bd_ih0, const float* __restrict__ bd_hh0,
    const float* __restrict__ bd_ih1, const float* __restrict__ bd_hh1,
    const float* __restrict__ fcb1, const float* __restrict__ fcw2,
    const float* __restrict__ fcb2,
    float* __restrict__ out) {
    extern __shared__ ull sm[];
    ull* h0s = sm;                 // 896
    ull* h1s = h0s + 896;          // 896
    ull* xs  = h1s + 896;          // 112
    ull* gil = xs + 112;           // 2688
    ull* gih = gil + NP * 384;     // 2688
    ull* ghl = gih + NP * 384;     // 2688
    ull* ghh = ghl + NP * 384;     // 2688
    ull* fch   = ghh + NP * 384;   // 448
    ull* pred2 = fch + NP * 64;    // 8
    float* sb    = reinterpret_cast<float*>(pred2 + 8);   // 8*384
    float* sfcb1 = sb + 8 * 384;
    float* sw2   = sfcb1 + 64;

    const int tid  = threadIdx.x;
    const int half = (tid >= 384) ? 1 : 0;
    const int r384 = half ? tid - 384 : tid;
    const int rg   = (r384 >= 192) ? 1 : 0;   // rowgroup: pairs 0-3 / 4-6
    const int jt   = rg ? r384 - 192 : r384;  // column base (also +192)
    const int rowbase = blockIdx.x * NROW;

    // init
    for (int i = tid; i < 2 * 896; i += NT) h0s[i] = 0ull;
    if (tid < 384) {
        const float* bsrc[8] = {be_ih0, be_hh0, be_ih1, be_hh1,
                                bd_ih0, bd_hh0, bd_ih1, bd_hh1};
#pragma unroll
        for (int a = 0; a < 8; a++) sb[a * 384 + tid] = bsrc[a][tid];
    }
    if (tid < 64) { sfcb1[tid] = fcb1[tid]; sw2[tid] = fcw2[tid]; }
    if (tid < 8) pred2[tid] = 0ull;
    __syncthreads();

    // =============================== encoder ===============================
    for (int t = 0; t < TIN; t++) {
        // stage x_t (pair-packed, clamp OOB rows)
        for (int i = tid; i < NP * NFEAT; i += NT) {
            int p = i >> 4, c = i & 15;
            int ra = rowbase + 2 * p;
            int rb = ra + 1;
            if (ra > BATCH - 1) ra = BATCH - 1;
            if (rb > BATCH - 1) rb = BATCH - 1;
            float a = x[(size_t)ra * TIN * NFEAT + (size_t)t * NFEAT + c];
            float b = x[(size_t)rb * TIN * NFEAT + (size_t)t * NFEAT + c];
            xs[p * NFEAT + c] = pk2(a, b);
        }
        __syncthreads();

        // layer 0
        gemm_d<NFEAT>(g_We0i, xs, half ? gih : gil, jt, half, rg);
        gemm_d<HID>(g_We0h, h0s, half ? ghh : ghl, jt, half, rg);
        __syncthreads();
        gates_phase(h0s, gil, gih, ghl, ghh, sb + 0 * 384, sb + 1 * 384, tid);
        __syncthreads();

        // layer 1 (input = new h0)
        gemm_d<HID>(g_We1i, h0s, half ? gih : gil, jt, half, rg);
        gemm_d<HID>(g_We1h, h1s, half ? ghh : ghl, jt, half, rg);
        __syncthreads();
        gates_phase(h1s, gil, gih, ghl, ghh, sb + 2 * 384, sb + 3 * 384, tid);
        __syncthreads();
    }

    // =============================== decoder ===============================
    const float b2 = __ldg(fcb2);
    const int pbase = rg ? 4 : 0;
    const int pcnt  = rg ? 3 : 4;

    for (int t = 0; t < TOUT; t++) {
        // cell 0: gi = pred * Wih0 (K=1): lo half computes, hi half zeros
        if (!half) {
            float wA = __ldg(&dwih0[jt]);
            float wB = __ldg(&dwih0[jt + 192]);
            ull WA = pk2(wA, wA), WB = pk2(wB, wB);
            for (int p = pbase; p < pbase + pcnt; p++) {
                gil[p * 384 + jt]       = ffma2(pred2[p], WA, 0ull);
                gil[p * 384 + jt + 192] = ffma2(pred2[p], WB, 0ull);
            }
        } else {
            for (int p = pbase; p < pbase + pcnt; p++) {
                gih[p * 384 + jt]       = 0ull;
                gih[p * 384 + jt + 192] = 0ull;
            }
        }
        gemm_d<HID>(g_Wd0h, h0s, half ? ghh : ghl, jt, half, rg);
        __syncthreads();
        gates_phase(h0s, gil, gih, ghl, ghh, sb + 4 * 384, sb + 5 * 384, tid);
        __syncthreads();

        // cell 1 (input = new h0)
        gemm_d<HID>(g_Wd1i, h0s, half ? gih : gil, jt, half, rg);
        gemm_d<HID>(g_Wd1h, h1s, half ? ghh : ghl, jt, half, rg);
        __syncthreads();
        gates_phase(h1s, gil, gih, ghl, ghh, sb + 6 * 384, sb + 7 * 384, tid);
        __syncthreads();

        // fc1: 64 cols x NP pairs, K=128, relu
        if (tid < 64 * NP) {
            int c = tid & 63, p = tid >> 6;
            ull a0 = 0ull, a1 = 0ull;
            const float2* W = reinterpret_cast<const float2*>(g_Wfc1);
#pragma unroll 8
            for (int k2 = 0; k2 < HID / 2; k2++) {
                float2 w = __ldg(&W[k2 * 64 + c]);
                ulonglong2 hv =
                    *reinterpret_cast<const ulonglong2*>(&h1s[p * HID + 2 * k2]);
                a0 = ffma2(hv.x, pk2(w.x, w.x), a0);
                a1 = ffma2(hv.y, pk2(w.y, w.y), a1);
            }
            float2 s0 = upk(a0), s1 = upk(a1);
            float vx = fmaxf(s0.x + s1.x + sfcb1[c], 0.0f);
            float vy = fmaxf(s0.y + s1.y + sfcb1[c], 0.0f);
            fch[p * 64 + c] = pk2(vx, vy);
        }
        __syncthreads();

        // fc2 + writeback + feedback: warp p handles pair p
        if (tid < 32 * NP) {
            int p = tid >> 5, l = tid & 31;
            ull a = ffma2(fch[p * 64 + 2 * l], pk2(sw2[2 * l], sw2[2 * l]), 0ull);
            a = ffma2(fch[p * 64 + 2 * l + 1],
                      pk2(sw2[2 * l + 1], sw2[2 * l + 1]), a);
            float2 s = upk(a);
#pragma unroll
            for (int o = 16; o > 0; o >>= 1) {
                s.x += __shfl_down_sync(0xffffffffu, s.x, o);
                s.y += __shfl_down_sync(0xffffffffu, s.y, o);
            }
            if (l == 0) {
                float px = fmaxf(s.x + b2, 0.0f);
                float py = fmaxf(s.y + b2, 0.0f);
                pred2[p] = pk2(px, py);
                int ra = rowbase + 2 * p;
                if (ra < BATCH) out[(size_t)ra * TOUT + t] = px;
                if (ra + 1 < BATCH) out[(size_t)(ra + 1) * TOUT + t] = py;
            }
        }
        __syncthreads();
    }
}

// ---------------------------------------------------------------------------
extern "C" void kernel_launch(void* const* d_in, const int* in_sizes, int n_in,
                              void* d_out, int out_size) {
    (void)in_sizes; (void)n_in; (void)out_size;
    const float* x     = (const float*)d_in[0];
    const float* eWih0 = (const float*)d_in[1];
    const float* eWhh0 = (const float*)d_in[2];
    const float* ebih0 = (const float*)d_in[3];
    const float* ebhh0 = (const float*)d_in[4];
    const float* eWih1 = (const float*)d_in[5];
    const float* eWhh1 = (const float*)d_in[6];
    const float* ebih1 = (const float*)d_in[7];
    const float* ebhh1 = (const float*)d_in[8];
    const float* dWih0 = (const float*)d_in[9];
    const float* dWhh0 = (const float*)d_in[10];
    const float* dbih0 = (const float*)d_in[11];
    const float* dbhh0 = (const float*)d_in[12];
    const float* dWih1 = (const float*)d_in[13];
    const float* dWhh1 = (const float*)d_in[14];
    const float* dbih1 = (const float*)d_in[15];
    const float* dbhh1 = (const float*)d_in[16];
    const float* fcW1  = (const float*)d_in[17];
    const float* fcb1  = (const float*)d_in[18];
    const float* fcW2  = (const float*)d_in[19];
    const float* fcb2  = (const float*)d_in[20];
    float* out = (float*)d_out;

    cudaFuncSetAttribute(gru_main, cudaFuncAttributeMaxDynamicSharedMemorySize,
                         (int)SMEM_BYTES);

    // one fused transpose launch (also makes ncu -s 5 land on gru_main)
    {
        int total = NFEAT * 384 + 6 * HID * 384 + HID * 64;
        int thr = 256;
        tr_all<<<(total + thr - 1) / thr, thr>>>(eWih0, eWhh0, eWih1, eWhh1,
                                                 dWhh0, dWih1, dWhh1, fcW1);
    }

    gru_main<<<NBLK, NT, SMEM_BYTES>>>(x,
                                       ebih0, ebhh0, ebih1, ebhh1,
                                       dWih0,
                                       dbih0, dbhh0, dbih1, dbhh1,
                                       fcb1, fcW2, fcb2,
                                       out);
}